// round 12
// baseline (speedup 1.0000x reference)
#include <cuda_runtime.h>

// Problem constants
#define B_SZ     32
#define C_INPUT  64
#define L_IN     8192
#define L_OUT    8186
#define PF       128

typedef unsigned long long u64;

__device__ __forceinline__ u64 pk2(float lo, float hi) {
    u64 r; asm("mov.b64 %0, {%1, %2};" : "=l"(r) : "f"(lo), "f"(hi)); return r;
}
__device__ __forceinline__ u64 dup2(float v) { return pk2(v, v); }
__device__ __forceinline__ void fma2(u64& d, u64 a, u64 b) {
    asm("fma.rn.f32x2 %0, %1, %2, %0;" : "+l"(d) : "l"(a), "l"(b));
}
__device__ __forceinline__ float2 up2(u64 v) {
    float lo, hi; asm("mov.b64 {%0, %1}, %2;" : "=f"(lo), "=f"(hi) : "l"(v));
    return make_float2(lo, hi);
}

// ---------------- scratch: intermediate feature maps --------------------
// ch 0-5: m7a (valid s in [0,8190)); ch 6-11: m10b; 12-17: m15b (u in [0,8186))
// position p stored at index p+16; pads are never written -> causal zeros.
#define GROW 8448
__device__ float g_mid[B_SZ][18][GROW];

extern __shared__ float smem[];

// ======================= KERNEL A: layers 1 + 2 =========================
#define TA       256      // time-tile
#define NTA      384      // threads (12 warps)
#define A_XST    264      // x row stride (262 used)
#define A_M1ST   264      // m1 row stride (260 used)
#define A_SX     0
#define A_SM1    (A_SX  + 64 * A_XST)         // 16896
#define A_SW1    (A_SM1 + 18 * A_M1ST)        // 21648: [9 ocpair][64 c][8]: j*2+s
#define A_SW2    (A_SW1 + 9 * 64 * 8)         // 26256: [12 oc][6 c][8] dup
#define A_FLOATS (A_SW2 + 12 * 6 * 8)         // 26832
#define A_BYTES  (A_FLOATS * 4)               // 107328 -> 2 CTAs/SM (24 warps)

__global__ void __launch_bounds__(NTA, 2) kernelA(
    const float* __restrict__ x,
    const float* __restrict__ w7_1, const float* __restrict__ w10_1,
    const float* __restrict__ w15_1,
    const float* __restrict__ w10_3, const float* __restrict__ w15_3)
{
    float* sx  = smem + A_SX;
    float* sm1 = smem + A_SM1;   // rows: 0-5 m7a, 6-11 m10a, 12-17 m15a
    float* sw1 = smem + A_SW1;
    float* sw2 = smem + A_SW2;

    const int tid  = threadIdx.x;
    const int warp = tid >> 5;
    const int lane = tid & 31;
    const int b    = blockIdx.y;
    const int s0   = blockIdx.x * TA;

    // stage layer-1 weights: sw1[(op*64+c)*8 + j*2 + s] = w_{2*op+s}[c*3+j]
    for (int i = tid; i < 18 * 192; i += NTA) {
        int o = i / 192, r = i % 192, c = r / 3, j = r % 3;
        float v = (o < 6) ? w7_1[i] : (o < 12) ? w10_1[i - 1152] : w15_1[i - 2304];
        sw1[(((o >> 1) * 64 + c) * 8) + j * 2 + (o & 1)] = v;
    }
    // stage layer-2 weights duplicated: sw2[(oc*6+c)*8 + j*2 + {0,1}]
    for (int i = tid; i < 12 * 18; i += NTA) {
        int o = i / 18, r = i % 18, c = r / 3, j = r % 3;
        float v = (o < 6) ? w10_3[i] : w15_3[i - 108];
        int base = (o * 6 + c) * 8 + j * 2;
        sw2[base] = v; sw2[base + 1] = v;
    }
    // stage x: 64 ch x 264 slots (262 real positions [s0, s0+262), zero past L_IN)
    {
        const float* xb = x + (long long)b * C_INPUT * L_IN;
        for (int c = warp; c < C_INPUT; c += 12) {
            const float* xc  = xb + (long long)c * L_IN;
            float*       sxc = sx + c * A_XST;
            for (int i = lane; i < 66; i += 32) {
                int g = s0 + 4 * i;
                float4 v;
                if (g + 3 < L_IN) {
                    v = *(const float4*)(xc + g);
                } else {
                    v.x = (g     < L_IN) ? xc[g]     : 0.f;
                    v.y = (g + 1 < L_IN) ? xc[g + 1] : 0.f;
                    v.z = (g + 2 < L_IN) ? xc[g + 2] : 0.f;
                    v.w = (g + 3 < L_IN) ? xc[g + 3] : 0.f;
                }
                *(float4*)(sxc + 4 * i) = v;
            }
        }
    }
    __syncthreads();

    // ---- layer 1: warp = (oc-group q3 of 3 pairs) x (64-pos block blk) ----
    {
        const int q3  = warp % 3;
        const int blk = warp / 3;                 // 0..3
        const int p0  = blk * 64 + lane * 2;      // outputs p0, p0+1
        const int op0 = q3 * 3;
        u64 A0[3] = {0,0,0}, A1[3] = {0,0,0};
        #pragma unroll 2
        for (int c = 0; c < 64; c++) {
            const float* xc = sx + c * A_XST + p0;
            float2 va = *(const float2*)xc;        // d0,d1 (8B aligned)
            float2 vb = *(const float2*)(xc + 2);  // d2,d3
            u64 D0 = dup2(va.x), D1 = dup2(va.y), D2 = dup2(vb.x), D3 = dup2(vb.y);
            #pragma unroll
            for (int i = 0; i < 3; i++) {
                const float* wc = sw1 + ((op0 + i) * 64 + c) * 8;
                ulonglong2 w01 = *(const ulonglong2*)wc;   // (W0, W1) dup-pairs
                u64 W2 = *(const u64*)(wc + 4);
                fma2(A0[i], w01.x, D0); fma2(A0[i], w01.y, D1); fma2(A0[i], W2, D2);
                fma2(A1[i], w01.x, D1); fma2(A1[i], w01.y, D2); fma2(A1[i], W2, D3);
            }
        }
        #pragma unroll
        for (int i = 0; i < 3; i++) {
            float* r0 = sm1 + (2 * (op0 + i))     * A_M1ST + p0;
            float* r1 = sm1 + (2 * (op0 + i) + 1) * A_M1ST + p0;
            float2 v0 = up2(A0[i]), v1 = up2(A1[i]);
            r0[0] = fmaxf(v0.x, 0.f); r0[1] = fmaxf(v1.x, 0.f);
            r1[0] = fmaxf(v0.y, 0.f); r1[1] = fmaxf(v1.y, 0.f);
        }
    }
    // ---- layer 1 TAIL: positions 256..259, needed as layer-2 halo.
    if (tid < 9) {
        const int q  = tid;
        const int p0 = 256;
        u64 A0 = 0, A1 = 0, A2 = 0, A3 = 0;
        for (int c = 0; c < 64; c++) {
            const float* xc = sx + c * A_XST + p0;
            float4 va = *(const float4*)xc;        // d0..d3
            float2 vb = *(const float2*)(xc + 4);  // d4,d5
            u64 D0 = dup2(va.x), D1 = dup2(va.y), D2 = dup2(va.z),
                D3 = dup2(va.w), D4 = dup2(vb.x), D5 = dup2(vb.y);
            const float* wc = sw1 + (q * 64 + c) * 8;
            ulonglong2 w01 = *(const ulonglong2*)wc;
            u64 W2 = *(const u64*)(wc + 4);
            fma2(A0, w01.x, D0); fma2(A0, w01.y, D1); fma2(A0, W2, D2);
            fma2(A1, w01.x, D1); fma2(A1, w01.y, D2); fma2(A1, W2, D3);
            fma2(A2, w01.x, D2); fma2(A2, w01.y, D3); fma2(A2, W2, D4);
            fma2(A3, w01.x, D3); fma2(A3, w01.y, D4); fma2(A3, W2, D5);
        }
        float* r0 = sm1 + (2 * q)     * A_M1ST + p0;
        float* r1 = sm1 + (2 * q + 1) * A_M1ST + p0;
        float2 v;
        v = up2(A0); r0[0] = fmaxf(v.x, 0.f); r1[0] = fmaxf(v.y, 0.f);
        v = up2(A1); r0[1] = fmaxf(v.x, 0.f); r1[1] = fmaxf(v.y, 0.f);
        v = up2(A2); r0[2] = fmaxf(v.x, 0.f); r1[2] = fmaxf(v.y, 0.f);
        v = up2(A3); r0[3] = fmaxf(v.x, 0.f); r1[3] = fmaxf(v.y, 0.f);
    }
    __syncthreads();

    // ---- layer 2: 12 ocs x 256 positions; warp = oc, lane = 8 positions ----
    if (warp < 12) {
        int oc = warp;
        int p0 = lane * 8;                         // outputs u0..u0+7 (local)
        int br = oc / 6;
        const float* minp = sm1 + (6 + br * 6) * A_M1ST + p0;
        const float* wrow = sw2 + oc * 48;
        u64 A0 = 0, A1 = 0, A2 = 0, A3 = 0;
        #pragma unroll
        for (int c = 0; c < 6; c++) {
            const float* mc = minp + c * A_M1ST;
            ulonglong2 d01 = *(const ulonglong2*)(mc + 0);   // pairs 0,1
            ulonglong2 d23 = *(const ulonglong2*)(mc + 4);   // pairs 2,3
            ulonglong2 d45 = *(const ulonglong2*)(mc + 8);   // pairs 4,5
            const float* wc = wrow + c * 8;
            ulonglong2 w01 = *(const ulonglong2*)wc;
            u64 W2 = *(const u64*)(wc + 4);
            fma2(A0, w01.x, d01.x); fma2(A0, w01.y, d01.y); fma2(A0, W2, d23.x);
            fma2(A1, w01.x, d01.y); fma2(A1, w01.y, d23.x); fma2(A1, W2, d23.y);
            fma2(A2, w01.x, d23.x); fma2(A2, w01.y, d23.y); fma2(A2, W2, d45.x);
            fma2(A3, w01.x, d23.y); fma2(A3, w01.y, d45.x); fma2(A3, W2, d45.y);
        }
        float* gr = &g_mid[b][6 + oc][0];
        u64 accs[4] = {A0, A1, A2, A3};
        #pragma unroll
        for (int k = 0; k < 4; k++) {
            int u = s0 + p0 + 2 * k;
            float2 v = up2(accs[k]);
            v.x = fmaxf(v.x, 0.f); v.y = fmaxf(v.y, 0.f);
            if (u + 1 < 8186)      *(float2*)(gr + u + 16) = v;
            else if (u < 8186)     gr[u + 16] = v.x;
        }
    }

    // ---- m7a export: 6 ch x 64 float4 blocks = 384 items, one per thread ----
    {
        int ch = tid / 64, p0 = (tid % 64) * 4;
        int s  = s0 + p0;
        float4 v = *(const float4*)(sm1 + ch * A_M1ST + p0);   // already relu'd
        float* gr = &g_mid[b][ch][s + 16];
        if (s + 3 < 8190) {
            *(float4*)gr = v;
        } else {
            if (s     < 8190) gr[0] = v.x;
            if (s + 1 < 8190) gr[1] = v.y;
            if (s + 2 < 8190) gr[2] = v.z;
            if (s + 3 < 8190) gr[3] = v.w;
        }
    }
}

// =============== KERNEL B slices: one branch per kernel ==================
// smem: s6[6][140] staged channels + w[128*24] weights = 15648 B -> 4 CTAs/SM,
// launch_bounds(256,4) caps regs at 64 -> 32 warps/SM.
#define TS       128
#define THREADS  256
#define B_ST     140
#define B_W      (6 * B_ST)          // 840: weight area offset
#define B_FLOATS (B_W + 128 * 24)    // 3912
#define B_BYTES  (B_FLOATS * 4)      // 15648

__device__ __forceinline__ void storep4(float* outb, int o, int t, u64 A01, u64 A23)
{
    float2 v0 = up2(A01), v1 = up2(A23);
    v0.x = fmaxf(v0.x, 0.f); v0.y = fmaxf(v0.y, 0.f);
    v1.x = fmaxf(v1.x, 0.f); v1.y = fmaxf(v1.y, 0.f);
    float* op = outb + (long long)o * L_OUT + t;
    if (t + 3 < L_OUT) {
        __stcs((float2*)op,       v0);
        __stcs((float2*)(op + 2), v1);
    } else {
        if (t     < L_OUT) op[0] = v0.x;
        if (t + 1 < L_OUT) op[1] = v0.y;
        if (t + 2 < L_OUT) op[2] = v1.x;
        if (t + 3 < L_OUT) op[3] = v1.y;
    }
}

// stage 6 channels [ch0..ch0+5] x 140 positions from scratch
__device__ __forceinline__ void stage6(float* s6, int b, int ch0, int t0, int tid)
{
    for (int i = tid; i < 6 * B_ST; i += THREADS) {
        int ch = i / B_ST, j = i % B_ST;
        s6[i] = g_mid[b][ch0 + ch][t0 + 8 + j];
    }
}

// ----- branch 7: kw=3 d=2, in ch 0-5, out ch 0-127 -----
__global__ void __launch_bounds__(THREADS, 4) kernelB7(
    const float* __restrict__ w7_3, float* __restrict__ out)
{
    float* s6 = smem;
    float* sw = smem + B_W;
    const int tid = threadIdx.x;
    const int b   = blockIdx.y;
    const int t0  = blockIdx.x * TS;

    for (int i = tid; i < 128 * 18; i += THREADS) {
        int o = i / 18, r = i % 18, c = r / 3, j = r % 3;
        sw[(o * 6 + c) * 4 + j] = w7_3[i];
    }
    stage6(s6, b, 0, t0, tid);
    __syncthreads();

    const int g = tid >> 5, lane = tid & 31;
    const int p0 = lane * 4, t = t0 + p0;
    float* outb = out + (long long)b * (3 * PF) * L_OUT;

    u64 P[6][4];
    #pragma unroll
    for (int c = 0; c < 6; c++) {
        const ulonglong2* mc = (const ulonglong2*)(s6 + c * B_ST + p0 + 8);
        ulonglong2 lo = mc[0], hi = mc[1];
        P[c][0] = lo.x; P[c][1] = lo.y; P[c][2] = hi.x; P[c][3] = hi.y;
    }
    #pragma unroll 2
    for (int k = 0; k < 16; k++) {
        int o = g * 16 + k;
        const float4* wrow = (const float4*)(sw + o * 24);
        u64 A01 = 0, A23 = 0;
        #pragma unroll
        for (int c = 0; c < 6; c++) {
            float4 w = wrow[c];
            u64 W0 = dup2(w.x), W1 = dup2(w.y), W2 = dup2(w.z);
            fma2(A01, W0, P[c][0]); fma2(A01, W1, P[c][1]); fma2(A01, W2, P[c][2]);
            fma2(A23, W0, P[c][1]); fma2(A23, W1, P[c][2]); fma2(A23, W2, P[c][3]);
        }
        storep4(outb, o, t, A01, A23);
    }
}

// ----- branch 10: kw=2 d=4, in ch 6-11, out ch 128-255 -----
__global__ void __launch_bounds__(THREADS, 4) kernelB10(
    const float* __restrict__ w10_5, float* __restrict__ out)
{
    float* s6 = smem;
    float* sw = smem + B_W;
    const int tid = threadIdx.x;
    const int b   = blockIdx.y;
    const int t0  = blockIdx.x * TS;

    for (int i = tid; i < 128 * 12; i += THREADS) {
        int o = i / 12, r = i % 12, c = r / 2, j = r % 2;
        int base = (o * 6 + c) * 4 + j * 2;
        float v = w10_5[i];
        sw[base] = v; sw[base + 1] = v;      // dup pairs
    }
    stage6(s6, b, 6, t0, tid);
    __syncthreads();

    const int g = tid >> 5, lane = tid & 31;
    const int p0 = lane * 4, t = t0 + p0;
    float* outb = out + (long long)b * (3 * PF) * L_OUT;

    u64 P[6][4];
    #pragma unroll
    for (int c = 0; c < 6; c++) {
        const ulonglong2* mc = (const ulonglong2*)(s6 + c * B_ST + p0 + 4);
        ulonglong2 lo = mc[0], hi = mc[1];
        P[c][0] = lo.x; P[c][1] = lo.y; P[c][2] = hi.x; P[c][3] = hi.y;
    }
    #pragma unroll 2
    for (int k = 0; k < 16; k++) {
        int o = g * 16 + k;
        const float* wrow = sw + o * 24;
        u64 A01 = 0, A23 = 0;
        #pragma unroll
        for (int c = 0; c < 6; c++) {
            ulonglong2 w01 = *(const ulonglong2*)(wrow + c * 4);
            fma2(A01, w01.x, P[c][0]); fma2(A01, w01.y, P[c][2]);
            fma2(A23, w01.x, P[c][1]); fma2(A23, w01.y, P[c][3]);
        }
        storep4(outb, 128 + o, t, A01, A23);
    }
}

// ----- branch 15: kw=3 d=4, in ch 12-17, out ch 256-383 -----
__global__ void __launch_bounds__(THREADS, 4) kernelB15(
    const float* __restrict__ w15_5, float* __restrict__ out)
{
    float* s6 = smem;
    float* sw = smem + B_W;
    const int tid = threadIdx.x;
    const int b   = blockIdx.y;
    const int t0  = blockIdx.x * TS;

    for (int i = tid; i < 128 * 18; i += THREADS) {
        int o = i / 18, r = i % 18, c = r / 3, j = r % 3;
        sw[(o * 6 + c) * 4 + j] = w15_5[i];
    }
    stage6(s6, b, 12, t0, tid);
    __syncthreads();

    const int g = tid >> 5, lane = tid & 31;
    const int p0 = lane * 4;
    float* outb = out + (long long)b * (3 * PF) * L_OUT;

    #pragma unroll
    for (int r = 0; r < 2; r++) {
        u64 P[6][3];
        #pragma unroll
        for (int c = 0; c < 6; c++) {
            const float* mc = s6 + c * B_ST + p0 + 2 * r;
            P[c][0] = *(const u64*)(mc + 0);
            P[c][1] = *(const u64*)(mc + 4);
            P[c][2] = *(const u64*)(mc + 8);
        }
        #pragma unroll 2
        for (int k = 0; k < 16; k++) {
            int o = g * 16 + k;
            const float4* wrow = (const float4*)(sw + o * 24);
            u64 A = 0;
            #pragma unroll
            for (int c = 0; c < 6; c++) {
                float4 w = wrow[c];
                fma2(A, dup2(w.x), P[c][0]);
                fma2(A, dup2(w.y), P[c][1]);
                fma2(A, dup2(w.z), P[c][2]);
            }
            float2 v = up2(A);
            v.x = fmaxf(v.x, 0.f); v.y = fmaxf(v.y, 0.f);
            int tt = t0 + p0 + 2 * r;
            float* op = outb + (long long)(256 + o) * L_OUT + tt;
            if (tt + 1 < L_OUT)      __stcs((float2*)op, v);
            else if (tt < L_OUT)     op[0] = v.x;
        }
    }
}

// ============================== launch ==================================
extern "C" void kernel_launch(void* const* d_in, const int* in_sizes, int n_in,
                              void* d_out, int out_size)
{
    const float* x     = (const float*)d_in[0];
    const float* w7_1  = (const float*)d_in[1];
    const float* w7_3  = (const float*)d_in[2];
    const float* w10_1 = (const float*)d_in[3];
    const float* w10_3 = (const float*)d_in[4];
    const float* w10_5 = (const float*)d_in[5];
    const float* w15_1 = (const float*)d_in[6];
    const float* w15_3 = (const float*)d_in[7];
    const float* w15_5 = (const float*)d_in[8];
    float* out = (float*)d_out;

    static bool attr_done = false;
    if (!attr_done) {
        cudaFuncSetAttribute(kernelA,   cudaFuncAttributeMaxDynamicSharedMemorySize, A_BYTES);
        cudaFuncSetAttribute(kernelB7,  cudaFuncAttributeMaxDynamicSharedMemorySize, B_BYTES);
        cudaFuncSetAttribute(kernelB10, cudaFuncAttributeMaxDynamicSharedMemorySize, B_BYTES);
        cudaFuncSetAttribute(kernelB15, cudaFuncAttributeMaxDynamicSharedMemorySize, B_BYTES);
        attr_done = true;
    }

    dim3 gridA(32, B_SZ);   // TA=256 tiles
    dim3 gridB(64, B_SZ);   // TS=128 tiles
    kernelA  <<<gridA, NTA,     A_BYTES>>>(x, w7_1, w10_1, w15_1, w10_3, w15_3);
    kernelB7 <<<gridB, THREADS, B_BYTES>>>(w7_3,  out);
    kernelB10<<<gridB, THREADS, B_BYTES>>>(w10_5, out);
    kernelB15<<<gridB, THREADS, B_BYTES>>>(w15_5, out);
}

// round 13
// speedup vs baseline: 1.0504x; 1.0504x over previous
#include <cuda_runtime.h>

// Problem constants
#define B_SZ     32
#define C_INPUT  64
#define L_IN     8192
#define L_OUT    8186
#define PF       128

// Pipelining: 2 groups of 16 batches; A on capture stream, B on s2.
#define NGROUP   2
#define GB       (B_SZ / NGROUP)

typedef unsigned long long u64;

__device__ __forceinline__ u64 pk2(float lo, float hi) {
    u64 r; asm("mov.b64 %0, {%1, %2};" : "=l"(r) : "f"(lo), "f"(hi)); return r;
}
__device__ __forceinline__ u64 dup2(float v) { return pk2(v, v); }
__device__ __forceinline__ void fma2(u64& d, u64 a, u64 b) {
    asm("fma.rn.f32x2 %0, %1, %2, %0;" : "+l"(d) : "l"(a), "l"(b));
}
__device__ __forceinline__ float2 up2(u64 v) {
    float lo, hi; asm("mov.b64 {%0, %1}, %2;" : "=f"(lo), "=f"(hi) : "l"(v));
    return make_float2(lo, hi);
}

// ---------------- scratch: intermediate feature maps --------------------
#define GROW 8448
__device__ float g_mid[B_SZ][18][GROW];

extern __shared__ float smem[];

// ======================= KERNEL A: layers 1 + 2 =========================
#define TA       256
#define NTA      384
#define A_XST    264
#define A_M1ST   264
#define A_SX     0
#define A_SM1    (A_SX  + 64 * A_XST)
#define A_SW1    (A_SM1 + 18 * A_M1ST)
#define A_SW2    (A_SW1 + 9 * 64 * 8)
#define A_FLOATS (A_SW2 + 12 * 6 * 8)
#define A_BYTES  (A_FLOATS * 4)               // 107328 -> 2 CTAs/SM

__global__ void __launch_bounds__(NTA, 2) kernelA(
    const float* __restrict__ x,
    const float* __restrict__ w7_1, const float* __restrict__ w10_1,
    const float* __restrict__ w15_1,
    const float* __restrict__ w10_3, const float* __restrict__ w15_3,
    int b0)
{
    float* sx  = smem + A_SX;
    float* sm1 = smem + A_SM1;
    float* sw1 = smem + A_SW1;
    float* sw2 = smem + A_SW2;

    const int tid  = threadIdx.x;
    const int warp = tid >> 5;
    const int lane = tid & 31;
    const int b    = blockIdx.y + b0;
    const int s0   = blockIdx.x * TA;

    for (int i = tid; i < 18 * 192; i += NTA) {
        int o = i / 192, r = i % 192, c = r / 3, j = r % 3;
        float v = (o < 6) ? w7_1[i] : (o < 12) ? w10_1[i - 1152] : w15_1[i - 2304];
        sw1[(((o >> 1) * 64 + c) * 8) + j * 2 + (o & 1)] = v;
    }
    for (int i = tid; i < 12 * 18; i += NTA) {
        int o = i / 18, r = i % 18, c = r / 3, j = r % 3;
        float v = (o < 6) ? w10_3[i] : w15_3[i - 108];
        int base = (o * 6 + c) * 8 + j * 2;
        sw2[base] = v; sw2[base + 1] = v;
    }
    {
        const float* xb = x + (long long)b * C_INPUT * L_IN;
        for (int c = warp; c < C_INPUT; c += 12) {
            const float* xc  = xb + (long long)c * L_IN;
            float*       sxc = sx + c * A_XST;
            for (int i = lane; i < 66; i += 32) {
                int g = s0 + 4 * i;
                float4 v;
                if (g + 3 < L_IN) {
                    v = *(const float4*)(xc + g);
                } else {
                    v.x = (g     < L_IN) ? xc[g]     : 0.f;
                    v.y = (g + 1 < L_IN) ? xc[g + 1] : 0.f;
                    v.z = (g + 2 < L_IN) ? xc[g + 2] : 0.f;
                    v.w = (g + 3 < L_IN) ? xc[g + 3] : 0.f;
                }
                *(float4*)(sxc + 4 * i) = v;
            }
        }
    }
    __syncthreads();

    // layer 1: warp = (oc-group q3 of 3 pairs) x (64-pos block)
    {
        const int q3  = warp % 3;
        const int blk = warp / 3;
        const int p0  = blk * 64 + lane * 2;
        const int op0 = q3 * 3;
        u64 A0[3] = {0,0,0}, A1[3] = {0,0,0};
        #pragma unroll 2
        for (int c = 0; c < 64; c++) {
            const float* xc = sx + c * A_XST + p0;
            float2 va = *(const float2*)xc;
            float2 vb = *(const float2*)(xc + 2);
            u64 D0 = dup2(va.x), D1 = dup2(va.y), D2 = dup2(vb.x), D3 = dup2(vb.y);
            #pragma unroll
            for (int i = 0; i < 3; i++) {
                const float* wc = sw1 + ((op0 + i) * 64 + c) * 8;
                ulonglong2 w01 = *(const ulonglong2*)wc;
                u64 W2 = *(const u64*)(wc + 4);
                fma2(A0[i], w01.x, D0); fma2(A0[i], w01.y, D1); fma2(A0[i], W2, D2);
                fma2(A1[i], w01.x, D1); fma2(A1[i], w01.y, D2); fma2(A1[i], W2, D3);
            }
        }
        #pragma unroll
        for (int i = 0; i < 3; i++) {
            float* r0 = sm1 + (2 * (op0 + i))     * A_M1ST + p0;
            float* r1 = sm1 + (2 * (op0 + i) + 1) * A_M1ST + p0;
            float2 v0 = up2(A0[i]), v1 = up2(A1[i]);
            r0[0] = fmaxf(v0.x, 0.f); r0[1] = fmaxf(v1.x, 0.f);
            r1[0] = fmaxf(v0.y, 0.f); r1[1] = fmaxf(v1.y, 0.f);
        }
    }
    // layer 1 TAIL: positions 256..259
    if (tid < 9) {
        const int q  = tid;
        const int p0 = 256;
        u64 A0 = 0, A1 = 0, A2 = 0, A3 = 0;
        for (int c = 0; c < 64; c++) {
            const float* xc = sx + c * A_XST + p0;
            float4 va = *(const float4*)xc;
            float2 vb = *(const float2*)(xc + 4);
            u64 D0 = dup2(va.x), D1 = dup2(va.y), D2 = dup2(va.z),
                D3 = dup2(va.w), D4 = dup2(vb.x), D5 = dup2(vb.y);
            const float* wc = sw1 + (q * 64 + c) * 8;
            ulonglong2 w01 = *(const ulonglong2*)wc;
            u64 W2 = *(const u64*)(wc + 4);
            fma2(A0, w01.x, D0); fma2(A0, w01.y, D1); fma2(A0, W2, D2);
            fma2(A1, w01.x, D1); fma2(A1, w01.y, D2); fma2(A1, W2, D3);
            fma2(A2, w01.x, D2); fma2(A2, w01.y, D3); fma2(A2, W2, D4);
            fma2(A3, w01.x, D3); fma2(A3, w01.y, D4); fma2(A3, W2, D5);
        }
        float* r0 = sm1 + (2 * q)     * A_M1ST + p0;
        float* r1 = sm1 + (2 * q + 1) * A_M1ST + p0;
        float2 v;
        v = up2(A0); r0[0] = fmaxf(v.x, 0.f); r1[0] = fmaxf(v.y, 0.f);
        v = up2(A1); r0[1] = fmaxf(v.x, 0.f); r1[1] = fmaxf(v.y, 0.f);
        v = up2(A2); r0[2] = fmaxf(v.x, 0.f); r1[2] = fmaxf(v.y, 0.f);
        v = up2(A3); r0[3] = fmaxf(v.x, 0.f); r1[3] = fmaxf(v.y, 0.f);
    }
    __syncthreads();

    // layer 2: 12 ocs x 256 positions
    if (warp < 12) {
        int oc = warp;
        int p0 = lane * 8;
        int br = oc / 6;
        const float* minp = sm1 + (6 + br * 6) * A_M1ST + p0;
        const float* wrow = sw2 + oc * 48;
        u64 A0 = 0, A1 = 0, A2 = 0, A3 = 0;
        #pragma unroll
        for (int c = 0; c < 6; c++) {
            const float* mc = minp + c * A_M1ST;
            ulonglong2 d01 = *(const ulonglong2*)(mc + 0);
            ulonglong2 d23 = *(const ulonglong2*)(mc + 4);
            ulonglong2 d45 = *(const ulonglong2*)(mc + 8);
            const float* wc = wrow + c * 8;
            ulonglong2 w01 = *(const ulonglong2*)wc;
            u64 W2 = *(const u64*)(wc + 4);
            fma2(A0, w01.x, d01.x); fma2(A0, w01.y, d01.y); fma2(A0, W2, d23.x);
            fma2(A1, w01.x, d01.y); fma2(A1, w01.y, d23.x); fma2(A1, W2, d23.y);
            fma2(A2, w01.x, d23.x); fma2(A2, w01.y, d23.y); fma2(A2, W2, d45.x);
            fma2(A3, w01.x, d23.y); fma2(A3, w01.y, d45.x); fma2(A3, W2, d45.y);
        }
        float* gr = &g_mid[b][6 + oc][0];
        u64 accs[4] = {A0, A1, A2, A3};
        #pragma unroll
        for (int k = 0; k < 4; k++) {
            int u = s0 + p0 + 2 * k;
            float2 v = up2(accs[k]);
            v.x = fmaxf(v.x, 0.f); v.y = fmaxf(v.y, 0.f);
            if (u + 1 < 8186)      *(float2*)(gr + u + 16) = v;
            else if (u < 8186)     gr[u + 16] = v.x;
        }
    }

    // m7a export
    {
        int ch = tid / 64, p0 = (tid % 64) * 4;
        int s  = s0 + p0;
        float4 v = *(const float4*)(sm1 + ch * A_M1ST + p0);
        float* gr = &g_mid[b][ch][s + 16];
        if (s + 3 < 8190) {
            *(float4*)gr = v;
        } else {
            if (s     < 8190) gr[0] = v.x;
            if (s + 1 < 8190) gr[1] = v.y;
            if (s + 2 < 8190) gr[2] = v.z;
            if (s + 3 < 8190) gr[3] = v.w;
        }
    }
}

// ======================= KERNEL B: final layer (R9 layout, 130us) ========
#define TS       128
#define THREADS  256
#define B_ST    140
#define B_S18   0
#define B_SW7   (B_S18 + 18 * B_ST)       // [128][6][8] dup (6 used)
#define B_SW10  (B_SW7 + 128 * 48)        // [128][6][4] dup pairs
#define B_SW15  (B_SW10 + 128 * 24)       // [128][6][8] dup
#define B_FLOATS (B_SW15 + 128 * 48)
#define B_BYTES  (B_FLOATS * 4)           // 71520 -> 3 CTAs/SM

__device__ __forceinline__ void storep4(float* outb, int o, int t, u64 A01, u64 A23)
{
    float2 v0 = up2(A01), v1 = up2(A23);
    v0.x = fmaxf(v0.x, 0.f); v0.y = fmaxf(v0.y, 0.f);
    v1.x = fmaxf(v1.x, 0.f); v1.y = fmaxf(v1.y, 0.f);
    float* op = outb + (long long)o * L_OUT + t;
    if (t + 3 < L_OUT) {
        __stcs((float2*)op,       v0);
        __stcs((float2*)(op + 2), v1);
    } else {
        if (t     < L_OUT) op[0] = v0.x;
        if (t + 1 < L_OUT) op[1] = v0.y;
        if (t + 2 < L_OUT) op[2] = v1.x;
        if (t + 3 < L_OUT) op[3] = v1.y;
    }
}

__global__ void __launch_bounds__(THREADS, 3) kernelB(
    const float* __restrict__ w7_3, const float* __restrict__ w10_5,
    const float* __restrict__ w15_5,
    float* __restrict__ out, int b0)
{
    float* s18  = smem + B_S18;
    float* sw7  = smem + B_SW7;
    float* sw10 = smem + B_SW10;
    float* sw15 = smem + B_SW15;

    const int tid = threadIdx.x;
    const int b   = blockIdx.y + b0;
    const int t0  = blockIdx.x * TS;

    for (int i = tid; i < 128 * 18; i += THREADS) {
        int o = i / 18, r = i % 18, c = r / 3, j = r % 3;
        int base = (o * 6 + c) * 8 + j * 2;
        float v7 = w7_3[i], v15 = w15_5[i];
        sw7 [base] = v7;  sw7 [base + 1] = v7;
        sw15[base] = v15; sw15[base + 1] = v15;
    }
    for (int i = tid; i < 128 * 12; i += THREADS) {
        int o = i / 12, r = i % 12, c = r / 2, j = r % 2;
        int base = (o * 6 + c) * 4 + j * 2;
        float v = w10_5[i];
        sw10[base] = v; sw10[base + 1] = v;
    }
    for (int i = tid; i < 18 * 140; i += THREADS) {
        int ch = i / 140, j = i % 140;
        s18[ch * B_ST + j] = g_mid[b][ch][t0 + 8 + j];
    }
    __syncthreads();

    const int g    = tid >> 5;
    const int lane = tid & 31;
    const int p0   = lane * 4;
    const int t    = t0 + p0;
    float* outb = out + (long long)b * (3 * PF) * L_OUT;

    // branch 7
    {
        u64 P[6][4];
        #pragma unroll
        for (int c = 0; c < 6; c++) {
            const ulonglong2* mc = (const ulonglong2*)(s18 + c * B_ST + p0 + 8);
            ulonglong2 lo = mc[0], hi = mc[1];
            P[c][0] = lo.x; P[c][1] = lo.y; P[c][2] = hi.x; P[c][3] = hi.y;
        }
        #pragma unroll 2
        for (int k = 0; k < 16; k++) {
            int o = g * 16 + k;
            const float* wrow = sw7 + o * 48;
            u64 A01 = 0, A23 = 0;
            #pragma unroll
            for (int c = 0; c < 6; c++) {
                const float* wc = wrow + c * 8;
                ulonglong2 w01 = *(const ulonglong2*)wc;
                u64 W2 = *(const u64*)(wc + 4);
                fma2(A01, w01.x, P[c][0]); fma2(A01, w01.y, P[c][1]); fma2(A01, W2, P[c][2]);
                fma2(A23, w01.x, P[c][1]); fma2(A23, w01.y, P[c][2]); fma2(A23, W2, P[c][3]);
            }
            storep4(outb, o, t, A01, A23);
        }
    }

    // branch 10
    {
        u64 P[6][4];
        #pragma unroll
        for (int c = 0; c < 6; c++) {
            const ulonglong2* mc = (const ulonglong2*)(s18 + (6 + c) * B_ST + p0 + 4);
            ulonglong2 lo = mc[0], hi = mc[1];
            P[c][0] = lo.x; P[c][1] = lo.y; P[c][2] = hi.x; P[c][3] = hi.y;
        }
        #pragma unroll 2
        for (int k = 0; k < 16; k++) {
            int o = g * 16 + k;
            const float* wrow = sw10 + o * 24;
            u64 A01 = 0, A23 = 0;
            #pragma unroll
            for (int c = 0; c < 6; c++) {
                ulonglong2 w01 = *(const ulonglong2*)(wrow + c * 4);
                fma2(A01, w01.x, P[c][0]); fma2(A01, w01.y, P[c][2]);
                fma2(A23, w01.x, P[c][1]); fma2(A23, w01.y, P[c][3]);
            }
            storep4(outb, 128 + o, t, A01, A23);
        }
    }

    // branch 15: two 2-position passes
    #pragma unroll
    for (int r = 0; r < 2; r++) {
        u64 P[6][3];
        #pragma unroll
        for (int c = 0; c < 6; c++) {
            const float* mc = s18 + (12 + c) * B_ST + p0 + 2 * r;
            P[c][0] = *(const u64*)(mc + 0);
            P[c][1] = *(const u64*)(mc + 4);
            P[c][2] = *(const u64*)(mc + 8);
        }
        #pragma unroll 2
        for (int k = 0; k < 16; k++) {
            int o = g * 16 + k;
            const float* wrow = sw15 + o * 48;
            u64 A = 0;
            #pragma unroll
            for (int c = 0; c < 6; c++) {
                const float* wc = wrow + c * 8;
                ulonglong2 w01 = *(const ulonglong2*)wc;
                u64 W2 = *(const u64*)(wc + 4);
                fma2(A, w01.x, P[c][0]);
                fma2(A, w01.y, P[c][1]);
                fma2(A, W2,    P[c][2]);
            }
            float2 v = up2(A);
            v.x = fmaxf(v.x, 0.f); v.y = fmaxf(v.y, 0.f);
            int tt = t + 2 * r;
            float* op = outb + (long long)(256 + o) * L_OUT + tt;
            if (tt + 1 < L_OUT)      __stcs((float2*)op, v);
            else if (tt < L_OUT)     op[0] = v.x;
        }
    }
}

// ============================== launch ==================================
extern "C" void kernel_launch(void* const* d_in, const int* in_sizes, int n_in,
                              void* d_out, int out_size)
{
    const float* x     = (const float*)d_in[0];
    const float* w7_1  = (const float*)d_in[1];
    const float* w7_3  = (const float*)d_in[2];
    const float* w10_1 = (const float*)d_in[3];
    const float* w10_3 = (const float*)d_in[4];
    const float* w10_5 = (const float*)d_in[5];
    const float* w15_1 = (const float*)d_in[6];
    const float* w15_3 = (const float*)d_in[7];
    const float* w15_5 = (const float*)d_in[8];
    float* out = (float*)d_out;

    static cudaStream_t s2 = nullptr;
    static cudaEvent_t evA[NGROUP];
    static cudaEvent_t evJoin;
    if (!s2) {
        cudaFuncSetAttribute(kernelA, cudaFuncAttributeMaxDynamicSharedMemorySize, A_BYTES);
        cudaFuncSetAttribute(kernelB, cudaFuncAttributeMaxDynamicSharedMemorySize, B_BYTES);
        cudaStreamCreateWithFlags(&s2, cudaStreamNonBlocking);
        for (int i = 0; i < NGROUP; i++)
            cudaEventCreateWithFlags(&evA[i], cudaEventDisableTiming);
        cudaEventCreateWithFlags(&evJoin, cudaEventDisableTiming);
    }

    dim3 gridA(32, GB);   // TA=256 tiles x 16 batches
    dim3 gridB(64, GB);   // TS=128 tiles x 16 batches

    for (int g = 0; g < NGROUP; g++) {
        kernelA<<<gridA, NTA, A_BYTES>>>(x, w7_1, w10_1, w15_1, w10_3, w15_3, g * GB);
        cudaEventRecord(evA[g], 0);
    }
    for (int g = 0; g < NGROUP; g++) {
        cudaStreamWaitEvent(s2, evA[g], 0);
        kernelB<<<gridB, THREADS, B_BYTES, s2>>>(w7_3, w10_5, w15_5, out, g * GB);
    }
    cudaEventRecord(evJoin, s2);
    cudaStreamWaitEvent(0, evJoin, 0);
}

// round 14
// speedup vs baseline: 1.1091x; 1.0559x over previous
#include <cuda_runtime.h>

// Problem constants
#define B_SZ     32
#define C_INPUT  64
#define L_IN     8192
#define L_OUT    8186
#define PF       128

typedef unsigned long long u64;

__device__ __forceinline__ u64 pk2(float lo, float hi) {
    u64 r; asm("mov.b64 %0, {%1, %2};" : "=l"(r) : "f"(lo), "f"(hi)); return r;
}
__device__ __forceinline__ u64 dup2(float v) { return pk2(v, v); }
__device__ __forceinline__ void fma2(u64& d, u64 a, u64 b) {
    asm("fma.rn.f32x2 %0, %1, %2, %0;" : "+l"(d) : "l"(a), "l"(b));
}
__device__ __forceinline__ float2 up2(u64 v) {
    float lo, hi; asm("mov.b64 {%0, %1}, %2;" : "=f"(lo), "=f"(hi) : "l"(v));
    return make_float2(lo, hi);
}

// ---------------- scratch: intermediate feature maps --------------------
// ch 0-5: m7a (valid s in [0,8190)); ch 6-11: m10b; 12-17: m15b (u in [0,8186))
// position p stored at index p+16; pads are never written -> causal zeros.
#define GROW 8448
__device__ float g_mid[B_SZ][18][GROW];

extern __shared__ float smem[];

// ======================= KERNEL A: layers 1 + 2 (R10, 91us) =============
#define TA       256
#define NTA      384
#define A_XST    264
#define A_M1ST   264
#define A_SX     0
#define A_SM1    (A_SX  + 64 * A_XST)
#define A_SW1    (A_SM1 + 18 * A_M1ST)
#define A_SW2    (A_SW1 + 9 * 64 * 8)
#define A_FLOATS (A_SW2 + 12 * 6 * 8)
#define A_BYTES  (A_FLOATS * 4)               // 107328 -> 2 CTAs/SM (24 warps)

__global__ void __launch_bounds__(NTA, 2) kernelA(
    const float* __restrict__ x,
    const float* __restrict__ w7_1, const float* __restrict__ w10_1,
    const float* __restrict__ w15_1,
    const float* __restrict__ w10_3, const float* __restrict__ w15_3)
{
    float* sx  = smem + A_SX;
    float* sm1 = smem + A_SM1;   // rows: 0-5 m7a, 6-11 m10a, 12-17 m15a
    float* sw1 = smem + A_SW1;
    float* sw2 = smem + A_SW2;

    const int tid  = threadIdx.x;
    const int warp = tid >> 5;
    const int lane = tid & 31;
    const int b    = blockIdx.y;
    const int s0   = blockIdx.x * TA;

    // stage layer-1 weights: sw1[(op*64+c)*8 + j*2 + s] = w_{2*op+s}[c*3+j]
    for (int i = tid; i < 18 * 192; i += NTA) {
        int o = i / 192, r = i % 192, c = r / 3, j = r % 3;
        float v = (o < 6) ? w7_1[i] : (o < 12) ? w10_1[i - 1152] : w15_1[i - 2304];
        sw1[(((o >> 1) * 64 + c) * 8) + j * 2 + (o & 1)] = v;
    }
    // stage layer-2 weights duplicated
    for (int i = tid; i < 12 * 18; i += NTA) {
        int o = i / 18, r = i % 18, c = r / 3, j = r % 3;
        float v = (o < 6) ? w10_3[i] : w15_3[i - 108];
        int base = (o * 6 + c) * 8 + j * 2;
        sw2[base] = v; sw2[base + 1] = v;
    }
    // stage x: 64 ch x 264 slots (262 real positions [s0, s0+262))
    {
        const float* xb = x + (long long)b * C_INPUT * L_IN;
        for (int c = warp; c < C_INPUT; c += 12) {
            const float* xc  = xb + (long long)c * L_IN;
            float*       sxc = sx + c * A_XST;
            for (int i = lane; i < 66; i += 32) {
                int g = s0 + 4 * i;
                float4 v;
                if (g + 3 < L_IN) {
                    v = *(const float4*)(xc + g);
                } else {
                    v.x = (g     < L_IN) ? xc[g]     : 0.f;
                    v.y = (g + 1 < L_IN) ? xc[g + 1] : 0.f;
                    v.z = (g + 2 < L_IN) ? xc[g + 2] : 0.f;
                    v.w = (g + 3 < L_IN) ? xc[g + 3] : 0.f;
                }
                *(float4*)(sxc + 4 * i) = v;
            }
        }
    }
    __syncthreads();

    // layer 1: warp = (oc-group q3 of 3 pairs) x (64-pos block)
    {
        const int q3  = warp % 3;
        const int blk = warp / 3;
        const int p0  = blk * 64 + lane * 2;
        const int op0 = q3 * 3;
        u64 A0[3] = {0,0,0}, A1[3] = {0,0,0};
        #pragma unroll 2
        for (int c = 0; c < 64; c++) {
            const float* xc = sx + c * A_XST + p0;
            float2 va = *(const float2*)xc;
            float2 vb = *(const float2*)(xc + 2);
            u64 D0 = dup2(va.x), D1 = dup2(va.y), D2 = dup2(vb.x), D3 = dup2(vb.y);
            #pragma unroll
            for (int i = 0; i < 3; i++) {
                const float* wc = sw1 + ((op0 + i) * 64 + c) * 8;
                ulonglong2 w01 = *(const ulonglong2*)wc;
                u64 W2 = *(const u64*)(wc + 4);
                fma2(A0[i], w01.x, D0); fma2(A0[i], w01.y, D1); fma2(A0[i], W2, D2);
                fma2(A1[i], w01.x, D1); fma2(A1[i], w01.y, D2); fma2(A1[i], W2, D3);
            }
        }
        #pragma unroll
        for (int i = 0; i < 3; i++) {
            float* r0 = sm1 + (2 * (op0 + i))     * A_M1ST + p0;
            float* r1 = sm1 + (2 * (op0 + i) + 1) * A_M1ST + p0;
            float2 v0 = up2(A0[i]), v1 = up2(A1[i]);
            r0[0] = fmaxf(v0.x, 0.f); r0[1] = fmaxf(v1.x, 0.f);
            r1[0] = fmaxf(v0.y, 0.f); r1[1] = fmaxf(v1.y, 0.f);
        }
    }
    // layer 1 TAIL: positions 256..259 (layer-2 halo)
    if (tid < 9) {
        const int q  = tid;
        const int p0 = 256;
        u64 A0 = 0, A1 = 0, A2 = 0, A3 = 0;
        for (int c = 0; c < 64; c++) {
            const float* xc = sx + c * A_XST + p0;
            float4 va = *(const float4*)xc;
            float2 vb = *(const float2*)(xc + 4);
            u64 D0 = dup2(va.x), D1 = dup2(va.y), D2 = dup2(va.z),
                D3 = dup2(va.w), D4 = dup2(vb.x), D5 = dup2(vb.y);
            const float* wc = sw1 + (q * 64 + c) * 8;
            ulonglong2 w01 = *(const ulonglong2*)wc;
            u64 W2 = *(const u64*)(wc + 4);
            fma2(A0, w01.x, D0); fma2(A0, w01.y, D1); fma2(A0, W2, D2);
            fma2(A1, w01.x, D1); fma2(A1, w01.y, D2); fma2(A1, W2, D3);
            fma2(A2, w01.x, D2); fma2(A2, w01.y, D3); fma2(A2, W2, D4);
            fma2(A3, w01.x, D3); fma2(A3, w01.y, D4); fma2(A3, W2, D5);
        }
        float* r0 = sm1 + (2 * q)     * A_M1ST + p0;
        float* r1 = sm1 + (2 * q + 1) * A_M1ST + p0;
        float2 v;
        v = up2(A0); r0[0] = fmaxf(v.x, 0.f); r1[0] = fmaxf(v.y, 0.f);
        v = up2(A1); r0[1] = fmaxf(v.x, 0.f); r1[1] = fmaxf(v.y, 0.f);
        v = up2(A2); r0[2] = fmaxf(v.x, 0.f); r1[2] = fmaxf(v.y, 0.f);
        v = up2(A3); r0[3] = fmaxf(v.x, 0.f); r1[3] = fmaxf(v.y, 0.f);
    }
    __syncthreads();

    // layer 2: 12 ocs x 256 positions; warp = oc, lane = 8 positions
    if (warp < 12) {
        int oc = warp;
        int p0 = lane * 8;
        int br = oc / 6;
        const float* minp = sm1 + (6 + br * 6) * A_M1ST + p0;
        const float* wrow = sw2 + oc * 48;
        u64 A0 = 0, A1 = 0, A2 = 0, A3 = 0;
        #pragma unroll
        for (int c = 0; c < 6; c++) {
            const float* mc = minp + c * A_M1ST;
            ulonglong2 d01 = *(const ulonglong2*)(mc + 0);
            ulonglong2 d23 = *(const ulonglong2*)(mc + 4);
            ulonglong2 d45 = *(const ulonglong2*)(mc + 8);
            const float* wc = wrow + c * 8;
            ulonglong2 w01 = *(const ulonglong2*)wc;
            u64 W2 = *(const u64*)(wc + 4);
            fma2(A0, w01.x, d01.x); fma2(A0, w01.y, d01.y); fma2(A0, W2, d23.x);
            fma2(A1, w01.x, d01.y); fma2(A1, w01.y, d23.x); fma2(A1, W2, d23.y);
            fma2(A2, w01.x, d23.x); fma2(A2, w01.y, d23.y); fma2(A2, W2, d45.x);
            fma2(A3, w01.x, d23.y); fma2(A3, w01.y, d45.x); fma2(A3, W2, d45.y);
        }
        float* gr = &g_mid[b][6 + oc][0];
        u64 accs[4] = {A0, A1, A2, A3};
        #pragma unroll
        for (int k = 0; k < 4; k++) {
            int u = s0 + p0 + 2 * k;
            float2 v = up2(accs[k]);
            v.x = fmaxf(v.x, 0.f); v.y = fmaxf(v.y, 0.f);
            if (u + 1 < 8186)      *(float2*)(gr + u + 16) = v;
            else if (u < 8186)     gr[u + 16] = v.x;
        }
    }

    // m7a export: 6 ch x 64 float4 blocks, one per thread
    {
        int ch = tid / 64, p0 = (tid % 64) * 4;
        int s  = s0 + p0;
        float4 v = *(const float4*)(sm1 + ch * A_M1ST + p0);
        float* gr = &g_mid[b][ch][s + 16];
        if (s + 3 < 8190) {
            *(float4*)gr = v;
        } else {
            if (s     < 8190) gr[0] = v.x;
            if (s + 1 < 8190) gr[1] = v.y;
            if (s + 2 < 8190) gr[2] = v.z;
            if (s + 3 < 8190) gr[3] = v.w;
        }
    }
}

// ======================= KERNEL B: final layer (R9 layout, 130us) ========
#define TS       128
#define THREADS  256
#define B_ST    140
#define B_S18   0
#define B_SW7   (B_S18 + 18 * B_ST)       // [128][6][8] dup (6 used)
#define B_SW10  (B_SW7 + 128 * 48)        // [128][6][4] dup pairs
#define B_SW15  (B_SW10 + 128 * 24)       // [128][6][8] dup
#define B_FLOATS (B_SW15 + 128 * 48)
#define B_BYTES  (B_FLOATS * 4)           // 71520 -> 3 CTAs/SM

__device__ __forceinline__ void storep4(float* outb, int o, int t, u64 A01, u64 A23)
{
    float2 v0 = up2(A01), v1 = up2(A23);
    v0.x = fmaxf(v0.x, 0.f); v0.y = fmaxf(v0.y, 0.f);
    v1.x = fmaxf(v1.x, 0.f); v1.y = fmaxf(v1.y, 0.f);
    float* op = outb + (long long)o * L_OUT + t;
    if (t + 3 < L_OUT) {
        __stcs((float2*)op,       v0);
        __stcs((float2*)(op + 2), v1);
    } else {
        if (t     < L_OUT) op[0] = v0.x;
        if (t + 1 < L_OUT) op[1] = v0.y;
        if (t + 2 < L_OUT) op[2] = v1.x;
        if (t + 3 < L_OUT) op[3] = v1.y;
    }
}

__global__ void __launch_bounds__(THREADS, 3) kernelB(
    const float* __restrict__ w7_3, const float* __restrict__ w10_5,
    const float* __restrict__ w15_5,
    float* __restrict__ out)
{
    float* s18  = smem + B_S18;    // [18][140], local j <-> global t0-8+j
    float* sw7  = smem + B_SW7;
    float* sw10 = smem + B_SW10;
    float* sw15 = smem + B_SW15;

    const int tid = threadIdx.x;
    const int b   = blockIdx.y;
    const int t0  = blockIdx.x * TS;

    for (int i = tid; i < 128 * 18; i += THREADS) {
        int o = i / 18, r = i % 18, c = r / 3, j = r % 3;
        int base = (o * 6 + c) * 8 + j * 2;
        float v7 = w7_3[i], v15 = w15_5[i];
        sw7 [base] = v7;  sw7 [base + 1] = v7;
        sw15[base] = v15; sw15[base + 1] = v15;
    }
    for (int i = tid; i < 128 * 12; i += THREADS) {
        int o = i / 12, r = i % 12, c = r / 2, j = r % 2;
        int base = (o * 6 + c) * 4 + j * 2;
        float v = w10_5[i];
        sw10[base] = v; sw10[base + 1] = v;
    }
    for (int i = tid; i < 18 * 140; i += THREADS) {
        int ch = i / 140, j = i % 140;
        s18[ch * B_ST + j] = g_mid[b][ch][t0 + 8 + j];
    }
    __syncthreads();

    const int g    = tid >> 5;
    const int lane = tid & 31;
    const int p0   = lane * 4;
    const int t    = t0 + p0;
    float* outb = out + (long long)b * (3 * PF) * L_OUT;

    // branch 7: rows 0-5, pairs at local p0+8+2j
    {
        u64 P[6][4];
        #pragma unroll
        for (int c = 0; c < 6; c++) {
            const ulonglong2* mc = (const ulonglong2*)(s18 + c * B_ST + p0 + 8);
            ulonglong2 lo = mc[0], hi = mc[1];
            P[c][0] = lo.x; P[c][1] = lo.y; P[c][2] = hi.x; P[c][3] = hi.y;
        }
        #pragma unroll 2
        for (int k = 0; k < 16; k++) {
            int o = g * 16 + k;
            const float* wrow = sw7 + o * 48;
            u64 A01 = 0, A23 = 0;
            #pragma unroll
            for (int c = 0; c < 6; c++) {
                const float* wc = wrow + c * 8;
                ulonglong2 w01 = *(const ulonglong2*)wc;
                u64 W2 = *(const u64*)(wc + 4);
                fma2(A01, w01.x, P[c][0]); fma2(A01, w01.y, P[c][1]); fma2(A01, W2, P[c][2]);
                fma2(A23, w01.x, P[c][1]); fma2(A23, w01.y, P[c][2]); fma2(A23, W2, P[c][3]);
            }
            storep4(outb, o, t, A01, A23);
        }
    }

    // branch 10: rows 6-11, pairs at local p0+4+4j
    {
        u64 P[6][4];
        #pragma unroll
        for (int c = 0; c < 6; c++) {
            const ulonglong2* mc = (const ulonglong2*)(s18 + (6 + c) * B_ST + p0 + 4);
            ulonglong2 lo = mc[0], hi = mc[1];
            P[c][0] = lo.x; P[c][1] = lo.y; P[c][2] = hi.x; P[c][3] = hi.y;
        }
        #pragma unroll 2
        for (int k = 0; k < 16; k++) {
            int o = g * 16 + k;
            const float* wrow = sw10 + o * 24;
            u64 A01 = 0, A23 = 0;
            #pragma unroll
            for (int c = 0; c < 6; c++) {
                ulonglong2 w01 = *(const ulonglong2*)(wrow + c * 4);
                fma2(A01, w01.x, P[c][0]); fma2(A01, w01.y, P[c][2]);
                fma2(A23, w01.x, P[c][1]); fma2(A23, w01.y, P[c][3]);
            }
            storep4(outb, 128 + o, t, A01, A23);
        }
    }

    // branch 15: rows 12-17, two 2-position passes, taps p0+2r+4j
    #pragma unroll
    for (int r = 0; r < 2; r++) {
        u64 P[6][3];
        #pragma unroll
        for (int c = 0; c < 6; c++) {
            const float* mc = s18 + (12 + c) * B_ST + p0 + 2 * r;
            P[c][0] = *(const u64*)(mc + 0);
            P[c][1] = *(const u64*)(mc + 4);
            P[c][2] = *(const u64*)(mc + 8);
        }
        #pragma unroll 2
        for (int k = 0; k < 16; k++) {
            int o = g * 16 + k;
            const float* wrow = sw15 + o * 48;
            u64 A = 0;
            #pragma unroll
            for (int c = 0; c < 6; c++) {
                const float* wc = wrow + c * 8;
                ulonglong2 w01 = *(const ulonglong2*)wc;
                u64 W2 = *(const u64*)(wc + 4);
                fma2(A, w01.x, P[c][0]);
                fma2(A, w01.y, P[c][1]);
                fma2(A, W2,    P[c][2]);
            }
            float2 v = up2(A);
            v.x = fmaxf(v.x, 0.f); v.y = fmaxf(v.y, 0.f);
            int tt = t + 2 * r;
            float* op = outb + (long long)(256 + o) * L_OUT + tt;
            if (tt + 1 < L_OUT)      __stcs((float2*)op, v);
            else if (tt < L_OUT)     op[0] = v.x;
        }
    }
}

// ============================== launch ==================================
extern "C" void kernel_launch(void* const* d_in, const int* in_sizes, int n_in,
                              void* d_out, int out_size)
{
    const float* x     = (const float*)d_in[0];
    const float* w7_1  = (const float*)d_in[1];
    const float* w7_3  = (const float*)d_in[2];
    const float* w10_1 = (const float*)d_in[3];
    const float* w10_3 = (const float*)d_in[4];
    const float* w10_5 = (const float*)d_in[5];
    const float* w15_1 = (const float*)d_in[6];
    const float* w15_3 = (const float*)d_in[7];
    const float* w15_5 = (const float*)d_in[8];
    float* out = (float*)d_out;

    static bool attr_done = false;
    if (!attr_done) {
        cudaFuncSetAttribute(kernelA, cudaFuncAttributeMaxDynamicSharedMemorySize, A_BYTES);
        cudaFuncSetAttribute(kernelB, cudaFuncAttributeMaxDynamicSharedMemorySize, B_BYTES);
        attr_done = true;
    }

    dim3 gridA(32, B_SZ);   // TA=256 tiles
    dim3 gridB(64, B_SZ);   // TS=128 tiles
    kernelA<<<gridA, NTA,     A_BYTES>>>(x, w7_1, w10_1, w15_1, w10_3, w15_3);
    kernelB<<<gridB, THREADS, B_BYTES>>>(w7_3, w10_5, w15_5, out);
}